// round 14
// baseline (speedup 1.0000x reference)
#include <cuda_runtime.h>
#include <cstdint>

// OcrEmbedding: out[b,t,:] = sum_{s=0..3, id!=0} table[id[b,t,s], :]
// B=32, T=512, S=4, D=256, V=50000.
// d_in[0] = subtoken_ids (int32, B*T*S), d_in[1] = table (float32, V*D)
// Output: float32, B*T*D.
//
// FINAL champion (R12 configuration, best measured: 10.688us).
// One warp per token row; each lane owns an aligned 32B chunk (lane*8 floats).
// Each subtoken gather is a single warp-level LDG.256 = 1024B = one full
// table row. Branches on id are warp-uniform (skip pad-row loads).
//
// The kernel runs at the measured sm_103a random-gather floor: ~84MB of L2
// traffic at ~7.9 TB/s. Rounds 1-13 tested LDG.32/.128/.256, cp.async, TMA
// bulk (serial / double-buffered / warp-specialized ring), spatial hybrids,
// L2 evict policies, persistent single-wave, id prefetch, branch-free
// masking, and CTA sizes 128/256/512 - all land within [10.69, 11.01]us.

#define BT (32 * 512)    // 16384 token rows

struct F8 { float v[8]; };

__device__ __forceinline__ F8 ldg256(const float* p) {
    F8 r;
    asm volatile("ld.global.nc.v8.f32 {%0,%1,%2,%3,%4,%5,%6,%7}, [%8];"
                 : "=f"(r.v[0]), "=f"(r.v[1]), "=f"(r.v[2]), "=f"(r.v[3]),
                   "=f"(r.v[4]), "=f"(r.v[5]), "=f"(r.v[6]), "=f"(r.v[7])
                 : "l"(p));
    return r;
}

__device__ __forceinline__ void stg256(float* p, const F8& r) {
    asm volatile("st.global.v8.f32 [%0], {%1,%2,%3,%4,%5,%6,%7,%8};"
                 :: "l"(p),
                    "f"(r.v[0]), "f"(r.v[1]), "f"(r.v[2]), "f"(r.v[3]),
                    "f"(r.v[4]), "f"(r.v[5]), "f"(r.v[6]), "f"(r.v[7])
                 : "memory");
}

__global__ __launch_bounds__(256) void ocr_embed_v8_kernel(
    const int* __restrict__ ids,          // [BT*4]
    const float* __restrict__ table,      // [V*256]
    float* __restrict__ out)              // [BT*256]
{
    const int gid  = blockIdx.x * 256 + threadIdx.x;
    const int row  = gid >> 5;            // one warp per token row
    const int lane = gid & 31;            // 32B chunk: floats [lane*8, lane*8+8)
    const int off  = lane * 8;

    const int4 id = __ldg((const int4*)(ids + row * 4));  // warp-broadcast

    F8 s;
    #pragma unroll
    for (int i = 0; i < 8; i++) s.v[i] = 0.f;

    if (id.x != 0) {
        F8 a = ldg256(table + (size_t)id.x * 256 + off);
        #pragma unroll
        for (int i = 0; i < 8; i++) s.v[i] += a.v[i];
    }
    if (id.y != 0) {
        F8 a = ldg256(table + (size_t)id.y * 256 + off);
        #pragma unroll
        for (int i = 0; i < 8; i++) s.v[i] += a.v[i];
    }
    if (id.z != 0) {
        F8 a = ldg256(table + (size_t)id.z * 256 + off);
        #pragma unroll
        for (int i = 0; i < 8; i++) s.v[i] += a.v[i];
    }
    if (id.w != 0) {
        F8 a = ldg256(table + (size_t)id.w * 256 + off);
        #pragma unroll
        for (int i = 0; i < 8; i++) s.v[i] += a.v[i];
    }

    stg256(out + (size_t)row * 256 + off, s);
}

extern "C" void kernel_launch(void* const* d_in, const int* in_sizes, int n_in,
                              void* d_out, int out_size)
{
    const int*   ids   = (const int*)d_in[0];
    const float* table = (const float*)d_in[1];
    float*       out   = (float*)d_out;

    const int total   = BT * 32;          // one warp per row
    const int threads = 256;
    const int blocks  = total / threads;  // 2048

    ocr_embed_v8_kernel<<<blocks, threads>>>(ids, table, out);
}

// round 15
// speedup vs baseline: 1.0299x; 1.0299x over previous
#include <cuda_runtime.h>
#include <cstdint>

// OcrEmbedding: out[b,t,:] = sum_{s=0..3, id!=0} table[id[b,t,s], :]
// B=32, T=512, S=4, D=256, V=50000.
// d_in[0] = subtoken_ids (int32, B*T*S), d_in[1] = table (float32, V*D)
// Output: float32, B*T*D.
//
// FINAL champion (R12 config; best measured 10.688us, run variance +-0.3us).
// One warp per token row; each lane owns an aligned 32B chunk (8 floats).
// Each subtoken gather is one warp-level LDG.256 = 1024B = a full table row;
// warp-uniform branches skip pad-row (id==0) loads. Output stored with .cs
// (evict-first: never re-read, preserves L2 for the table).
//
// Kernel sits at the measured sm_103a floor: ~84MB L2 traffic @ ~7.9TB/s
// (random 1KB-gather LTS ceiling). Rounds 1-14 tested LDG.32/.128/.256,
// cp.async, TMA bulk (serial/double-buffered/warp-specialized), spatial
// hybrids, L2 evict policies, persistent single-wave, id prefetch,
// branch-free masking, CTA sizes 128/256/512: all in [10.69, 11.01]us.

#define BT (32 * 512)    // 16384 token rows

struct F8 { float v[8]; };

__device__ __forceinline__ F8 ldg256(const float* p) {
    F8 r;
    asm volatile("ld.global.nc.v8.f32 {%0,%1,%2,%3,%4,%5,%6,%7}, [%8];"
                 : "=f"(r.v[0]), "=f"(r.v[1]), "=f"(r.v[2]), "=f"(r.v[3]),
                   "=f"(r.v[4]), "=f"(r.v[5]), "=f"(r.v[6]), "=f"(r.v[7])
                 : "l"(p));
    return r;
}

__device__ __forceinline__ void stg256_cs(float* p, const F8& r) {
    asm volatile("st.global.cs.v8.f32 [%0], {%1,%2,%3,%4,%5,%6,%7,%8};"
                 :: "l"(p),
                    "f"(r.v[0]), "f"(r.v[1]), "f"(r.v[2]), "f"(r.v[3]),
                    "f"(r.v[4]), "f"(r.v[5]), "f"(r.v[6]), "f"(r.v[7])
                 : "memory");
}

__global__ __launch_bounds__(256) void ocr_embed_v8_kernel(
    const int* __restrict__ ids,          // [BT*4]
    const float* __restrict__ table,      // [V*256]
    float* __restrict__ out)              // [BT*256]
{
    const int gid  = blockIdx.x * 256 + threadIdx.x;
    const int row  = gid >> 5;            // one warp per token row
    const int lane = gid & 31;            // 32B chunk: floats [lane*8, lane*8+8)
    const int off  = lane * 8;

    const int4 id = __ldg((const int4*)(ids + row * 4));  // warp-broadcast

    F8 s;
    #pragma unroll
    for (int i = 0; i < 8; i++) s.v[i] = 0.f;

    if (id.x != 0) {
        F8 a = ldg256(table + (size_t)id.x * 256 + off);
        #pragma unroll
        for (int i = 0; i < 8; i++) s.v[i] += a.v[i];
    }
    if (id.y != 0) {
        F8 a = ldg256(table + (size_t)id.y * 256 + off);
        #pragma unroll
        for (int i = 0; i < 8; i++) s.v[i] += a.v[i];
    }
    if (id.z != 0) {
        F8 a = ldg256(table + (size_t)id.z * 256 + off);
        #pragma unroll
        for (int i = 0; i < 8; i++) s.v[i] += a.v[i];
    }
    if (id.w != 0) {
        F8 a = ldg256(table + (size_t)id.w * 256 + off);
        #pragma unroll
        for (int i = 0; i < 8; i++) s.v[i] += a.v[i];
    }

    stg256_cs(out + (size_t)row * 256 + off, s);
}

extern "C" void kernel_launch(void* const* d_in, const int* in_sizes, int n_in,
                              void* d_out, int out_size)
{
    const int*   ids   = (const int*)d_in[0];
    const float* table = (const float*)d_in[1];
    float*       out   = (float*)d_out;

    const int total   = BT * 32;          // one warp per row
    const int threads = 256;
    const int blocks  = total / threads;  // 2048

    ocr_embed_v8_kernel<<<blocks, threads>>>(ids, table, out);
}